// round 8
// baseline (speedup 1.0000x reference)
#include <cuda_runtime.h>
#include <cstdint>

// TransitionGNN via legacy HMMA mma.sync.m16n8k16 (bf16, 3-pass hi/lo split).
// R8: 512 threads / 16 warps (4m x 4n), TB=128. Same total MMA work as R7 but
// 4 warps/SMSP for latency hiding (tensor-pipe utilization).
// B=8192, K=10, D=64, H=128, A=16, E=90, F=208.

#define KN 10
#define TB 128
#define NT 512

// ---- staged scratch (bf16 hi/lo, ldmatrix-ready) ----
__device__ __align__(16) unsigned char g_sHi[KN * 8192 * 128];   // [j][b][64d] 128B rows, swz
__device__ __align__(16) unsigned char g_sLo[KN * 8192 * 128];
__device__ __align__(16) unsigned char g_aHi[KN * 8192 * 32];    // [j][b][16a] 32B rows
__device__ __align__(16) unsigned char g_aLo[KN * 8192 * 32];
__device__ __align__(16) unsigned char g_WeHi[90 * 128 * 256];   // [e][128k][128h] 256B rows, swz
__device__ __align__(16) unsigned char g_WeLo[90 * 128 * 256];
__device__ __align__(16) unsigned char g_WnHi[KN * 208 * 128];   // [i][208f][64d] 128B rows, swz
__device__ __align__(16) unsigned char g_WnLo[KN * 208 * 128];

// ---- smem map (bytes) ----
#define SI_HI    0u
#define SI_LO    16384u
#define ACT_HI   32768u
#define ACT_LO   36864u
#define SJ_HI    40960u
#define SJ_LO    57344u
#define W0       73728u         // 2 bufs x (hi 32KB + lo 32KB)
#define BIASALL  204800u        // 9 x 512B f32
#define SMEM_TOTAL 209920
// node-phase aliases:
#define AGG_HI   73728u         // [128r][256B] swz  (W buf 0)
#define AGG_LO   106496u
#define WN_HI    139264u        // (W buf 1)
#define WN_LO    165888u

__device__ __forceinline__ void split2(float x0, float x1, uint32_t& h2, uint32_t& l2) {
    asm("cvt.rn.bf16x2.f32 %0, %1, %2;" : "=r"(h2) : "f"(x1), "f"(x0));
    float h0 = __uint_as_float(h2 << 16);
    float h1 = __uint_as_float(h2 & 0xFFFF0000u);
    asm("cvt.rn.bf16x2.f32 %0, %1, %2;" : "=r"(l2) : "f"(x1 - h1), "f"(x0 - h0));
}
__device__ __forceinline__ float tanha(float x) {
    float r; asm("tanh.approx.f32 %0, %1;" : "=f"(r) : "f"(x)); return r;
}
__device__ __forceinline__ void cp16(uint32_t s, const void* g) {
    asm volatile("cp.async.cg.shared.global [%0], [%1], 16;" :: "r"(s), "l"(g));
}
__device__ __forceinline__ void cpblk(uint32_t sdst, const void* gsrc, int bytes, int tid) {
    for (int off = tid * 16; off < bytes; off += NT * 16)
        cp16(sdst + off, (const char*)gsrc + off);
}
#define CP_COMMIT() asm volatile("cp.async.commit_group;")
#define CP_WAIT(n)  asm volatile("cp.async.wait_group %0;" :: "n"(n))

__device__ __forceinline__ void ldsm4(uint32_t a, uint32_t r[4]) {
    asm volatile("ldmatrix.sync.aligned.m8n8.x4.shared.b16 {%0,%1,%2,%3}, [%4];"
        : "=r"(r[0]), "=r"(r[1]), "=r"(r[2]), "=r"(r[3]) : "r"(a));
}
__device__ __forceinline__ void ldsm4t(uint32_t a, uint32_t r[4]) {
    asm volatile("ldmatrix.sync.aligned.m8n8.x4.trans.shared.b16 {%0,%1,%2,%3}, [%4];"
        : "=r"(r[0]), "=r"(r[1]), "=r"(r[2]), "=r"(r[3]) : "r"(a));
}
__device__ __forceinline__ void mma(float c[4], const uint32_t a[4], uint32_t b0, uint32_t b1) {
    asm volatile("mma.sync.aligned.m16n8k16.row.col.f32.bf16.bf16.f32 "
        "{%0,%1,%2,%3},{%4,%5,%6,%7},{%8,%9},{%0,%1,%2,%3};"
        : "+f"(c[0]), "+f"(c[1]), "+f"(c[2]), "+f"(c[3])
        : "r"(a[0]), "r"(a[1]), "r"(a[2]), "r"(a[3]), "r"(b0), "r"(b1));
}
__device__ __forceinline__ uint32_t ldsma(uint32_t base, int row0, int cs0, int stride, int lane) {
    int r = row0 + (lane & 15);
    return base + (uint32_t)(r * stride) + ((uint32_t)((cs0 + (lane >> 4)) ^ (r & 7)) << 4);
}

// ===================== prep kernel =====================
__global__ void prep_kernel(const float* __restrict__ states, const float* __restrict__ action,
                            const float* __restrict__ We, const float* __restrict__ Wn)
{
    int tid = blockIdx.x * blockDim.x + threadIdx.x;
    int NTH = gridDim.x * blockDim.x;
    for (int p = tid; p < KN * 8192 * 32; p += NTH) {
        int d2 = p & 31, b = (p >> 5) & 8191, j = p >> 18;
        float2 v = *(const float2*)&states[((size_t)b * KN + j) * 64 + 2 * d2];
        uint32_t h2, l2; split2(v.x, v.y, h2, l2);
        uint32_t off = ((uint32_t)(j * 8192 + b) << 7)
                     + ((uint32_t)(((d2 >> 2) ^ (b & 7))) << 4) + ((uint32_t)(d2 & 3) << 2);
        *(uint32_t*)(g_sHi + off) = h2;
        *(uint32_t*)(g_sLo + off) = l2;
    }
    for (int p = tid; p < KN * 8192 * 8; p += NTH) {
        int a2 = p & 7, b = (p >> 3) & 8191, j = p >> 16;
        float2 v = *(const float2*)&action[((size_t)b * KN + j) * 16 + 2 * a2];
        uint32_t h2, l2; split2(v.x, v.y, h2, l2);
        uint32_t off = ((uint32_t)(j * 8192 + b) << 5) + ((uint32_t)a2 << 2);
        *(uint32_t*)(g_aHi + off) = h2;
        *(uint32_t*)(g_aLo + off) = l2;
    }
    for (int p = tid; p < 90 * 128 * 64; p += NTH) {
        int h2i = p & 63, k = (p >> 6) & 127, e = p >> 13;
        float2 v = *(const float2*)&We[((size_t)e * 128 + k) * 128 + 2 * h2i];
        uint32_t h2, l2; split2(v.x, v.y, h2, l2);
        uint32_t off = ((uint32_t)(e * 128 + k) << 8)
                     + ((uint32_t)(((h2i >> 2) ^ (k & 7))) << 4) + ((uint32_t)(h2i & 3) << 2);
        *(uint32_t*)(g_WeHi + off) = h2;
        *(uint32_t*)(g_WeLo + off) = l2;
    }
    for (int p = tid; p < KN * 208 * 32; p += NTH) {
        int d2 = p & 31, fi = p >> 5;
        int f = fi % 208, i = fi / 208;
        float2 v = *(const float2*)&Wn[((size_t)i * 208 + f) * 64 + 2 * d2];
        uint32_t h2, l2; split2(v.x, v.y, h2, l2);
        uint32_t off = ((uint32_t)(i * 208 + f) << 7)
                     + ((uint32_t)(((d2 >> 2) ^ (f & 7))) << 4) + ((uint32_t)(d2 & 3) << 2);
        *(uint32_t*)(g_WnHi + off) = h2;
        *(uint32_t*)(g_WnLo + off) = l2;
    }
}

// ===================== main kernel =====================
extern "C" __global__ void __launch_bounds__(NT, 1)
gnn_hmma_kernel(const float* __restrict__ b_edge,   // [E,H]
                const float* __restrict__ b_node,   // [K,D]
                float* __restrict__ out)            // [B,K,D]
{
    extern __shared__ char smem[];
    const uint32_t sb = (uint32_t)__cvta_generic_to_shared(smem);

    const int i    = blockIdx.y;
    const int b0   = blockIdx.x * TB;
    const int tid  = threadIdx.x;
    const int lane = tid & 31;
    const int wid  = tid >> 5;
    const int wm   = wid & 3;    // 4 m-warps: rows 32*wm .. +31
    const int wn   = wid >> 2;   // 4 n-warps: edge cols 32*wn, node cols 16*wn
    const int m0   = 32 * wm;

    // ---- prologue ----
    cpblk(sb + SI_HI,  g_sHi + (size_t)(i * 8192 + b0) * 128, 16384, tid);
    cpblk(sb + SI_LO,  g_sLo + (size_t)(i * 8192 + b0) * 128, 16384, tid);
    cpblk(sb + ACT_HI, g_aHi + (size_t)(i * 8192 + b0) * 32,  4096, tid);
    cpblk(sb + ACT_LO, g_aLo + (size_t)(i * 8192 + b0) * 32,  4096, tid);
    {
        int j0 = (i == 0) ? 1 : 0;
        cpblk(sb + SJ_HI, g_sHi + (size_t)(j0 * 8192 + b0) * 128, 16384, tid);
        cpblk(sb + SJ_LO, g_sLo + (size_t)(j0 * 8192 + b0) * 128, 16384, tid);
        cpblk(sb + W0,          g_WeHi + (size_t)(i * 9) * 32768, 32768, tid);
        cpblk(sb + W0 + 32768,  g_WeLo + (size_t)(i * 9) * 32768, 32768, tid);
        cpblk(sb + BIASALL, b_edge + (size_t)(i * 9) * 128, 4608, tid);
    }
    CP_COMMIT();                                             // g0
    cpblk(sb + W0 + 65536,          g_WeHi + (size_t)(i * 9 + 1) * 32768, 32768, tid);
    cpblk(sb + W0 + 65536 + 32768,  g_WeLo + (size_t)(i * 9 + 1) * 32768, 32768, tid);
    CP_COMMIT();                                             // g1 (W1)

    float C[32], agg2[32];
    #pragma unroll
    for (int q = 0; q < 32; ++q) agg2[q] = 0.0f;

    // ---- edge loop ----
    #pragma unroll
    for (int t = 0; t < 9; ++t) {
        if (t == 0) { CP_WAIT(1); } else { CP_WAIT(2); }     // W_t (+ t==0: si/sj0/bias) ready
        __syncthreads();

        // init C from bias
        {
            const float* bs = (const float*)(smem + BIASALL) + t * 128;
            #pragma unroll
            for (int m = 0; m < 2; ++m)
                #pragma unroll
                for (int p = 0; p < 2; ++p)
                    #pragma unroll
                    for (int co = 0; co < 2; ++co) {
                        int h = 32 * wn + p * 16 + co * 8 + (lane & 3) * 2;
                        float2 bv = *(const float2*)&bs[h];
                        float* c = C + m * 16 + p * 8 + co * 4;
                        c[0] = bv.x; c[1] = bv.y; c[2] = bv.x; c[3] = bv.y;
                    }
        }

        const uint32_t wHi = sb + W0 + (uint32_t)(t & 1) * 65536u;
        const uint32_t wLo = wHi + 32768u;

        #pragma unroll
        for (int kk = 0; kk < 8; ++kk) {
            if (kk == 4) { CP_WAIT(1); __syncthreads(); }    // sj_t ready (t>=1)
            const uint32_t aHiB = (kk < 4) ? (sb + SI_HI) : (sb + SJ_HI);
            const uint32_t aLoB = (kk < 4) ? (sb + SI_LO) : (sb + SJ_LO);
            const int kl = kk & 3;
            uint32_t ah[2][4], al[2][4];
            ldsm4(ldsma(aHiB, m0,      2 * kl, 128, lane), ah[0]);
            ldsm4(ldsma(aHiB, m0 + 16, 2 * kl, 128, lane), ah[1]);
            ldsm4(ldsma(aLoB, m0,      2 * kl, 128, lane), al[0]);
            ldsm4(ldsma(aLoB, m0 + 16, 2 * kl, 128, lane), al[1]);
            const int krow = 16 * kk;
            uint32_t bh[2][4], bl[2][4];
            #pragma unroll
            for (int p = 0; p < 2; ++p) {
                ldsm4t(ldsma(wHi, krow, 4 * wn + 2 * p, 256, lane), bh[p]);
                ldsm4t(ldsma(wLo, krow, 4 * wn + 2 * p, 256, lane), bl[p]);
            }
            // pass hh (8 independent accumulators), then hl, then lh
            #pragma unroll
            for (int m = 0; m < 2; ++m)
                #pragma unroll
                for (int p = 0; p < 2; ++p) {
                    mma(C + m * 16 + p * 8,     ah[m], bh[p][0], bh[p][1]);
                    mma(C + m * 16 + p * 8 + 4, ah[m], bh[p][2], bh[p][3]);
                }
            #pragma unroll
            for (int m = 0; m < 2; ++m)
                #pragma unroll
                for (int p = 0; p < 2; ++p) {
                    mma(C + m * 16 + p * 8,     ah[m], bl[p][0], bl[p][1]);
                    mma(C + m * 16 + p * 8 + 4, ah[m], bl[p][2], bl[p][3]);
                }
            #pragma unroll
            for (int m = 0; m < 2; ++m)
                #pragma unroll
                for (int p = 0; p < 2; ++p) {
                    mma(C + m * 16 + p * 8,     al[m], bh[p][0], bh[p][1]);
                    mma(C + m * 16 + p * 8 + 4, al[m], bh[p][2], bh[p][3]);
                }
        }
        __syncthreads();   // sj_t + W_t fully consumed

        // prefetch: sj_{t+1}, then W_{t+2} or W_node
        if (t < 8) {
            int jn = (t + 1) + ((t + 1) >= i ? 1 : 0);
            cpblk(sb + SJ_HI, g_sHi + (size_t)(jn * 8192 + b0) * 128, 16384, tid);
            cpblk(sb + SJ_LO, g_sLo + (size_t)(jn * 8192 + b0) * 128, 16384, tid);
            CP_COMMIT();                                     // gA: sj_{t+1}
            if (t < 7) {
                uint32_t wb = sb + W0 + (uint32_t)(t & 1) * 65536u;
                cpblk(wb,          g_WeHi + (size_t)(i * 9 + t + 2) * 32768, 32768, tid);
                cpblk(wb + 32768,  g_WeLo + (size_t)(i * 9 + t + 2) * 32768, 32768, tid);
            } else {
                cpblk(sb + WN_HI, g_WnHi + (size_t)i * 26624, 26624, tid);
                cpblk(sb + WN_LO, g_WnLo + (size_t)i * 26624, 26624, tid);
            }
            CP_COMMIT();                                     // gB: W_{t+2} / WN
        }

        // epilogue (MUFU overlaps other warps' MMAs)
        #pragma unroll
        for (int q = 0; q < 32; ++q) agg2[q] += tanha(C[q]);
    }

    // ---- node phase: write agg as bf16 hi/lo A-tile [128r][128k] (aliases W buf 0) ----
    #pragma unroll
    for (int m = 0; m < 2; ++m)
        #pragma unroll
        for (int p = 0; p < 2; ++p)
            #pragma unroll
            for (int co = 0; co < 2; ++co) {
                int h = 32 * wn + p * 16 + co * 8 + (lane & 3) * 2;
                int idx = m * 16 + p * 8 + co * 4;
                #pragma unroll
                for (int hh = 0; hh < 2; ++hh) {
                    int r = m0 + m * 16 + (lane >> 2) + 8 * hh;
                    uint32_t h2, l2;
                    split2(agg2[idx + 2 * hh], agg2[idx + 2 * hh + 1], h2, l2);
                    uint32_t off = (uint32_t)(r * 256)
                                 + ((uint32_t)(((h >> 3) ^ (r & 7))) << 4)
                                 + ((uint32_t)(h & 7) << 1);
                    *(uint32_t*)(smem + AGG_HI + off) = h2;
                    *(uint32_t*)(smem + AGG_LO + off) = l2;
                }
            }
    CP_WAIT(0);          // W_node staged
    __syncthreads();

    // init C2 from node bias (each warp: 16 cols at 16*wn)
    float C2[16];
    #pragma unroll
    for (int m = 0; m < 2; ++m)
        #pragma unroll
        for (int co = 0; co < 2; ++co) {
            int d = 16 * wn + co * 8 + (lane & 3) * 2;
            float2 bn = *(const float2*)&b_node[(size_t)i * 64 + d];
            float* c = C2 + m * 8 + co * 4;
            c[0] = bn.x; c[1] = bn.y; c[2] = bn.x; c[3] = bn.y;
        }

    // node GEMM: 13 ks-steps of k16 over F=208
    #pragma unroll
    for (int ks = 0; ks < 13; ++ks) {
        uint32_t ah[2][4], al[2][4];
        if (ks < 4) {
            ldsm4(ldsma(sb + SI_HI, m0,      2 * ks, 128, lane), ah[0]);
            ldsm4(ldsma(sb + SI_HI, m0 + 16, 2 * ks, 128, lane), ah[1]);
            ldsm4(ldsma(sb + SI_LO, m0,      2 * ks, 128, lane), al[0]);
            ldsm4(ldsma(sb + SI_LO, m0 + 16, 2 * ks, 128, lane), al[1]);
        } else if (ks == 4) {
            #pragma unroll
            for (int m = 0; m < 2; ++m) {
                int r = m0 + m * 16 + (lane & 15);
                uint32_t ao = (uint32_t)(r * 32) + ((uint32_t)(lane >> 4) << 4);
                ldsm4(sb + ACT_HI + ao, ah[m]);
                ldsm4(sb + ACT_LO + ao, al[m]);
            }
        } else {
            ldsm4(ldsma(sb + AGG_HI, m0,      2 * (ks - 5), 256, lane), ah[0]);
            ldsm4(ldsma(sb + AGG_HI, m0 + 16, 2 * (ks - 5), 256, lane), ah[1]);
            ldsm4(ldsma(sb + AGG_LO, m0,      2 * (ks - 5), 256, lane), al[0]);
            ldsm4(ldsma(sb + AGG_LO, m0 + 16, 2 * (ks - 5), 256, lane), al[1]);
        }
        uint32_t bh[4], bl[4];
        ldsm4t(ldsma(sb + WN_HI, 16 * ks, 2 * wn, 128, lane), bh);
        ldsm4t(ldsma(sb + WN_LO, 16 * ks, 2 * wn, 128, lane), bl);
        #pragma unroll
        for (int m = 0; m < 2; ++m) {
            float* c0 = C2 + m * 8;
            float* c1 = C2 + m * 8 + 4;
            mma(c0, ah[m], bh[0], bh[1]); mma(c1, ah[m], bh[2], bh[3]);
            mma(c0, ah[m], bl[0], bl[1]); mma(c1, ah[m], bl[2], bl[3]);
            mma(c0, al[m], bh[0], bh[1]); mma(c1, al[m], bh[2], bh[3]);
        }
    }

    // ---- final epilogue: tanh + store ----
    #pragma unroll
    for (int m = 0; m < 2; ++m)
        #pragma unroll
        for (int co = 0; co < 2; ++co) {
            int d = 16 * wn + co * 8 + (lane & 3) * 2;
            int r0 = m0 + m * 16 + (lane >> 2);
            const float* c = C2 + m * 8 + co * 4;
            float2 v0 = { tanha(c[0]), tanha(c[1]) };
            float2 v1 = { tanha(c[2]), tanha(c[3]) };
            *(float2*)&out[((size_t)(b0 + r0)     * KN + i) * 64 + d] = v0;
            *(float2*)&out[((size_t)(b0 + r0 + 8) * KN + i) * 64 + d] = v1;
        }
}

extern "C" void kernel_launch(void* const* d_in, const int* in_sizes, int n_in,
                              void* d_out, int out_size)
{
    const float* states = (const float*)d_in[0];
    const float* action = (const float*)d_in[1];
    const float* W_edge = (const float*)d_in[2];
    const float* b_edge = (const float*)d_in[3];
    const float* W_node = (const float*)d_in[4];
    const float* b_node = (const float*)d_in[5];
    float* out = (float*)d_out;

    int B = in_sizes[0] / (KN * 64);   // 8192

    prep_kernel<<<2048, 256>>>(states, action, W_edge, W_node);

    cudaFuncSetAttribute(gnn_hmma_kernel,
                         cudaFuncAttributeMaxDynamicSharedMemorySize, SMEM_TOTAL);
    dim3 grid(B / TB, KN);
    gnn_hmma_kernel<<<grid, NT, SMEM_TOTAL>>>(b_edge, b_node, out);
}

// round 9
// speedup vs baseline: 1.2293x; 1.2293x over previous
#include <cuda_runtime.h>
#include <cstdint>

// TransitionGNN via legacy HMMA mma.sync.m16n8k16 (bf16, 3-pass hi/lo split).
// R9: 2 CTAs/SM (TB=64, 256 thr, smem ~104.5KB, regs<=128). Warp grid 2m x 4n.
// Single-buffered W; cross-CTA overlap hides load/barrier bubbles.
// B=8192, K=10, D=64, H=128, A=16, E=90, F=208.

#define KN 10
#define TB 64
#define NT 256

// ---- staged scratch (bf16 hi/lo, ldmatrix-ready) ----
__device__ __align__(16) unsigned char g_sHi[KN * 8192 * 128];   // [j][b][64d] 128B rows, swz
__device__ __align__(16) unsigned char g_sLo[KN * 8192 * 128];
__device__ __align__(16) unsigned char g_aHi[KN * 8192 * 32];    // [j][b][16a] 32B rows
__device__ __align__(16) unsigned char g_aLo[KN * 8192 * 32];
__device__ __align__(16) unsigned char g_WeHi[90 * 128 * 256];   // [e][128k][128h] 256B rows, swz
__device__ __align__(16) unsigned char g_WeLo[90 * 128 * 256];
__device__ __align__(16) unsigned char g_WnHi[KN * 208 * 128];   // [i][208f][64d] 128B rows, swz
__device__ __align__(16) unsigned char g_WnLo[KN * 208 * 128];

// ---- smem map (bytes), total 107008 (~104.5KB) => 2 CTAs/SM ----
#define SI_HI    0u          // 8KB  (64r x 128B)
#define SI_LO    8192u
#define ACT_HI   16384u      // 2KB  (64r x 32B)
#define ACT_LO   18432u
#define BIASALL  20480u      // 9 x 512B
#define SJ_HI    25088u      // 8KB
#define SJ_LO    33280u
#define WBASE    41472u      // 64KB: WE_HI 32KB + WE_LO 32KB
#define WE_HI    (WBASE)
#define WE_LO    (WBASE + 32768u)
#define SMEM_TOTAL 107008
// node-phase aliases inside WBASE:
#define AGG_HI   (WBASE)             // 16KB (64r x 256B)
#define AGG_LO   (WBASE + 16384u)    // 16KB
#define WN_HI    (WBASE + 32768u)    // chunk buffer <=14KB
#define WN_LO    (WBASE + 49152u)    // chunk buffer <=14KB

__device__ __forceinline__ void split2(float x0, float x1, uint32_t& h2, uint32_t& l2) {
    asm("cvt.rn.bf16x2.f32 %0, %1, %2;" : "=r"(h2) : "f"(x1), "f"(x0));
    float h0 = __uint_as_float(h2 << 16);
    float h1 = __uint_as_float(h2 & 0xFFFF0000u);
    asm("cvt.rn.bf16x2.f32 %0, %1, %2;" : "=r"(l2) : "f"(x1 - h1), "f"(x0 - h0));
}
__device__ __forceinline__ float tanha(float x) {
    float r; asm("tanh.approx.f32 %0, %1;" : "=f"(r) : "f"(x)); return r;
}
__device__ __forceinline__ void cp16(uint32_t s, const void* g) {
    asm volatile("cp.async.cg.shared.global [%0], [%1], 16;" :: "r"(s), "l"(g));
}
__device__ __forceinline__ void cpblk(uint32_t sdst, const void* gsrc, int bytes, int tid) {
    for (int off = tid * 16; off < bytes; off += NT * 16)
        cp16(sdst + off, (const char*)gsrc + off);
}
#define CP_COMMIT() asm volatile("cp.async.commit_group;")
#define CP_WAIT0()  asm volatile("cp.async.wait_group 0;")

__device__ __forceinline__ void ldsm4(uint32_t a, uint32_t r[4]) {
    asm volatile("ldmatrix.sync.aligned.m8n8.x4.shared.b16 {%0,%1,%2,%3}, [%4];"
        : "=r"(r[0]), "=r"(r[1]), "=r"(r[2]), "=r"(r[3]) : "r"(a));
}
__device__ __forceinline__ void ldsm4t(uint32_t a, uint32_t r[4]) {
    asm volatile("ldmatrix.sync.aligned.m8n8.x4.trans.shared.b16 {%0,%1,%2,%3}, [%4];"
        : "=r"(r[0]), "=r"(r[1]), "=r"(r[2]), "=r"(r[3]) : "r"(a));
}
__device__ __forceinline__ void mma(float c[4], const uint32_t a[4], uint32_t b0, uint32_t b1) {
    asm volatile("mma.sync.aligned.m16n8k16.row.col.f32.bf16.bf16.f32 "
        "{%0,%1,%2,%3},{%4,%5,%6,%7},{%8,%9},{%0,%1,%2,%3};"
        : "+f"(c[0]), "+f"(c[1]), "+f"(c[2]), "+f"(c[3])
        : "r"(a[0]), "r"(a[1]), "r"(a[2]), "r"(a[3]), "r"(b0), "r"(b1));
}
__device__ __forceinline__ uint32_t ldsma(uint32_t base, int row0, int cs0, int stride, int lane) {
    int r = row0 + (lane & 15);
    return base + (uint32_t)(r * stride) + ((uint32_t)((cs0 + (lane >> 4)) ^ (r & 7)) << 4);
}

// ===================== prep kernel =====================
__global__ void prep_kernel(const float* __restrict__ states, const float* __restrict__ action,
                            const float* __restrict__ We, const float* __restrict__ Wn)
{
    int tid = blockIdx.x * blockDim.x + threadIdx.x;
    int NTH = gridDim.x * blockDim.x;
    for (int p = tid; p < KN * 8192 * 32; p += NTH) {
        int d2 = p & 31, b = (p >> 5) & 8191, j = p >> 18;
        float2 v = *(const float2*)&states[((size_t)b * KN + j) * 64 + 2 * d2];
        uint32_t h2, l2; split2(v.x, v.y, h2, l2);
        uint32_t off = ((uint32_t)(j * 8192 + b) << 7)
                     + ((uint32_t)(((d2 >> 2) ^ (b & 7))) << 4) + ((uint32_t)(d2 & 3) << 2);
        *(uint32_t*)(g_sHi + off) = h2;
        *(uint32_t*)(g_sLo + off) = l2;
    }
    for (int p = tid; p < KN * 8192 * 8; p += NTH) {
        int a2 = p & 7, b = (p >> 3) & 8191, j = p >> 16;
        float2 v = *(const float2*)&action[((size_t)b * KN + j) * 16 + 2 * a2];
        uint32_t h2, l2; split2(v.x, v.y, h2, l2);
        uint32_t off = ((uint32_t)(j * 8192 + b) << 5) + ((uint32_t)a2 << 2);
        *(uint32_t*)(g_aHi + off) = h2;
        *(uint32_t*)(g_aLo + off) = l2;
    }
    for (int p = tid; p < 90 * 128 * 64; p += NTH) {
        int h2i = p & 63, k = (p >> 6) & 127, e = p >> 13;
        float2 v = *(const float2*)&We[((size_t)e * 128 + k) * 128 + 2 * h2i];
        uint32_t h2, l2; split2(v.x, v.y, h2, l2);
        uint32_t off = ((uint32_t)(e * 128 + k) << 8)
                     + ((uint32_t)(((h2i >> 2) ^ (k & 7))) << 4) + ((uint32_t)(h2i & 3) << 2);
        *(uint32_t*)(g_WeHi + off) = h2;
        *(uint32_t*)(g_WeLo + off) = l2;
    }
    for (int p = tid; p < KN * 208 * 32; p += NTH) {
        int d2 = p & 31, fi = p >> 5;
        int f = fi % 208, i = fi / 208;
        float2 v = *(const float2*)&Wn[((size_t)i * 208 + f) * 64 + 2 * d2];
        uint32_t h2, l2; split2(v.x, v.y, h2, l2);
        uint32_t off = ((uint32_t)(i * 208 + f) << 7)
                     + ((uint32_t)(((d2 >> 2) ^ (f & 7))) << 4) + ((uint32_t)(d2 & 3) << 2);
        *(uint32_t*)(g_WnHi + off) = h2;
        *(uint32_t*)(g_WnLo + off) = l2;
    }
}

// ===================== main kernel =====================
extern "C" __global__ void __launch_bounds__(NT, 2)
gnn_hmma_kernel(const float* __restrict__ b_edge,   // [E,H]
                const float* __restrict__ b_node,   // [K,D]
                float* __restrict__ out)            // [B,K,D]
{
    extern __shared__ char smem[];
    const uint32_t sb = (uint32_t)__cvta_generic_to_shared(smem);

    const int i    = blockIdx.y;
    const int b0   = blockIdx.x * TB;
    const int tid  = threadIdx.x;
    const int lane = tid & 31;
    const int wid  = tid >> 5;
    const int wm   = wid & 1;    // 2 m-warps: rows 32*wm .. +31
    const int wn   = wid >> 1;   // 4 n-warps: edge cols 32*wn, node cols 16*wn
    const int m0   = 32 * wm;

    // ---- prologue: si, act, bias, sj0, W0 (one group) ----
    cpblk(sb + SI_HI,  g_sHi + (size_t)(i * 8192 + b0) * 128, 8192, tid);
    cpblk(sb + SI_LO,  g_sLo + (size_t)(i * 8192 + b0) * 128, 8192, tid);
    cpblk(sb + ACT_HI, g_aHi + (size_t)(i * 8192 + b0) * 32,  2048, tid);
    cpblk(sb + ACT_LO, g_aLo + (size_t)(i * 8192 + b0) * 32,  2048, tid);
    cpblk(sb + BIASALL, b_edge + (size_t)(i * 9) * 128, 4608, tid);
    {
        int j0 = (i == 0) ? 1 : 0;
        cpblk(sb + SJ_HI, g_sHi + (size_t)(j0 * 8192 + b0) * 128, 8192, tid);
        cpblk(sb + SJ_LO, g_sLo + (size_t)(j0 * 8192 + b0) * 128, 8192, tid);
        cpblk(sb + WE_HI, g_WeHi + (size_t)(i * 9) * 32768, 32768, tid);
        cpblk(sb + WE_LO, g_WeLo + (size_t)(i * 9) * 32768, 32768, tid);
    }
    CP_COMMIT();

    float C[32], agg2[32];
    #pragma unroll
    for (int q = 0; q < 32; ++q) agg2[q] = 0.0f;

    // ---- edge loop ----
    #pragma unroll
    for (int t = 0; t < 9; ++t) {
        CP_WAIT0();
        __syncthreads();     // W_t, sj_t (and t==0: si/act/bias) visible

        // init C from bias
        {
            const float* bs = (const float*)(smem + BIASALL) + t * 128;
            #pragma unroll
            for (int m = 0; m < 2; ++m)
                #pragma unroll
                for (int p = 0; p < 2; ++p)
                    #pragma unroll
                    for (int co = 0; co < 2; ++co) {
                        int h = 32 * wn + p * 16 + co * 8 + (lane & 3) * 2;
                        float2 bv = *(const float2*)&bs[h];
                        float* c = C + m * 16 + p * 8 + co * 4;
                        c[0] = bv.x; c[1] = bv.y; c[2] = bv.x; c[3] = bv.y;
                    }
        }

        #pragma unroll
        for (int kk = 0; kk < 8; ++kk) {
            const uint32_t aHiB = (kk < 4) ? (sb + SI_HI) : (sb + SJ_HI);
            const uint32_t aLoB = (kk < 4) ? (sb + SI_LO) : (sb + SJ_LO);
            const int kl = kk & 3;
            uint32_t ah[2][4], al[2][4];
            ldsm4(ldsma(aHiB, m0,      2 * kl, 128, lane), ah[0]);
            ldsm4(ldsma(aHiB, m0 + 16, 2 * kl, 128, lane), ah[1]);
            ldsm4(ldsma(aLoB, m0,      2 * kl, 128, lane), al[0]);
            ldsm4(ldsma(aLoB, m0 + 16, 2 * kl, 128, lane), al[1]);
            const int krow = 16 * kk;
            uint32_t bh[2][4], bl[2][4];
            #pragma unroll
            for (int p = 0; p < 2; ++p) {
                ldsm4t(ldsma(sb + WE_HI, krow, 4 * wn + 2 * p, 256, lane), bh[p]);
                ldsm4t(ldsma(sb + WE_LO, krow, 4 * wn + 2 * p, 256, lane), bl[p]);
            }
            // pass hh (8 independent accumulators), then hl, then lh
            #pragma unroll
            for (int m = 0; m < 2; ++m)
                #pragma unroll
                for (int p = 0; p < 2; ++p) {
                    mma(C + m * 16 + p * 8,     ah[m], bh[p][0], bh[p][1]);
                    mma(C + m * 16 + p * 8 + 4, ah[m], bh[p][2], bh[p][3]);
                }
            #pragma unroll
            for (int m = 0; m < 2; ++m)
                #pragma unroll
                for (int p = 0; p < 2; ++p) {
                    mma(C + m * 16 + p * 8,     ah[m], bl[p][0], bl[p][1]);
                    mma(C + m * 16 + p * 8 + 4, ah[m], bl[p][2], bl[p][3]);
                }
            #pragma unroll
            for (int m = 0; m < 2; ++m)
                #pragma unroll
                for (int p = 0; p < 2; ++p) {
                    mma(C + m * 16 + p * 8,     al[m], bh[p][0], bh[p][1]);
                    mma(C + m * 16 + p * 8 + 4, al[m], bh[p][2], bh[p][3]);
                }
        }
        __syncthreads();   // all warps done reading W_t / sj_t

        // issue next loads (single buffers now free)
        if (t < 8) {
            int jn = (t + 1) + ((t + 1) >= i ? 1 : 0);
            cpblk(sb + SJ_HI, g_sHi + (size_t)(jn * 8192 + b0) * 128, 8192, tid);
            cpblk(sb + SJ_LO, g_sLo + (size_t)(jn * 8192 + b0) * 128, 8192, tid);
            cpblk(sb + WE_HI, g_WeHi + (size_t)(i * 9 + t + 1) * 32768, 32768, tid);
            cpblk(sb + WE_LO, g_WeLo + (size_t)(i * 9 + t + 1) * 32768, 32768, tid);
        } else {
            // node W chunk A: f-rows 0..111 (ks 0..6), 14336B each
            cpblk(sb + WN_HI, g_WnHi + (size_t)i * 26624, 14336, tid);
            cpblk(sb + WN_LO, g_WnLo + (size_t)i * 26624, 14336, tid);
        }
        CP_COMMIT();

        // epilogue (overlaps in-flight cp.async + other CTA's MMAs)
        #pragma unroll
        for (int q = 0; q < 32; ++q) agg2[q] += tanha(C[q]);
    }

    // ---- node phase: write agg as bf16 hi/lo A-tile [64r][128k] (aliases WE rows 0..63) ----
    #pragma unroll
    for (int m = 0; m < 2; ++m)
        #pragma unroll
        for (int p = 0; p < 2; ++p)
            #pragma unroll
            for (int co = 0; co < 2; ++co) {
                int h = 32 * wn + p * 16 + co * 8 + (lane & 3) * 2;
                int idx = m * 16 + p * 8 + co * 4;
                #pragma unroll
                for (int hh = 0; hh < 2; ++hh) {
                    int r = m0 + m * 16 + (lane >> 2) + 8 * hh;
                    uint32_t h2, l2;
                    split2(agg2[idx + 2 * hh], agg2[idx + 2 * hh + 1], h2, l2);
                    uint32_t off = (uint32_t)(r * 256)
                                 + ((uint32_t)(((h >> 3) ^ (r & 7))) << 4)
                                 + ((uint32_t)(h & 7) << 1);
                    *(uint32_t*)(smem + AGG_HI + off) = h2;
                    *(uint32_t*)(smem + AGG_LO + off) = l2;
                }
            }
    CP_WAIT0();          // WN chunk A staged
    __syncthreads();     // + AGG visible

    // init C2 from node bias (warp: 16 cols at 16*wn)
    float C2[16];
    #pragma unroll
    for (int m = 0; m < 2; ++m)
        #pragma unroll
        for (int co = 0; co < 2; ++co) {
            int d = 16 * wn + co * 8 + (lane & 3) * 2;
            float2 bn = *(const float2*)&b_node[(size_t)i * 64 + d];
            float* c = C2 + m * 8 + co * 4;
            c[0] = bn.x; c[1] = bn.y; c[2] = bn.x; c[3] = bn.y;
        }

    // node GEMM over F=208 in two WN chunks: ks 0..6 (rows 0..111), ks 7..12 (rows 112..207)
    #pragma unroll
    for (int chunk = 0; chunk < 2; ++chunk) {
        const int ksBeg = chunk ? 7 : 0;
        const int ksEnd = chunk ? 13 : 7;
        const int rBase = chunk ? 112 : 0;
        #pragma unroll
        for (int ks = ksBeg; ks < ksEnd; ++ks) {
            uint32_t ah[2][4], al[2][4];
            if (ks < 4) {
                ldsm4(ldsma(sb + SI_HI, m0,      2 * ks, 128, lane), ah[0]);
                ldsm4(ldsma(sb + SI_HI, m0 + 16, 2 * ks, 128, lane), ah[1]);
                ldsm4(ldsma(sb + SI_LO, m0,      2 * ks, 128, lane), al[0]);
                ldsm4(ldsma(sb + SI_LO, m0 + 16, 2 * ks, 128, lane), al[1]);
            } else if (ks == 4) {
                #pragma unroll
                for (int m = 0; m < 2; ++m) {
                    int r = m0 + m * 16 + (lane & 15);
                    uint32_t ao = (uint32_t)(r * 32) + ((uint32_t)(lane >> 4) << 4);
                    ldsm4(sb + ACT_HI + ao, ah[m]);
                    ldsm4(sb + ACT_LO + ao, al[m]);
                }
            } else {
                ldsm4(ldsma(sb + AGG_HI, m0,      2 * (ks - 5), 256, lane), ah[0]);
                ldsm4(ldsma(sb + AGG_HI, m0 + 16, 2 * (ks - 5), 256, lane), ah[1]);
                ldsm4(ldsma(sb + AGG_LO, m0,      2 * (ks - 5), 256, lane), al[0]);
                ldsm4(ldsma(sb + AGG_LO, m0 + 16, 2 * (ks - 5), 256, lane), al[1]);
            }
            uint32_t bh[4], bl[4];
            ldsm4t(ldsma(sb + WN_HI, 16 * ks - rBase, 2 * wn, 128, lane), bh);
            ldsm4t(ldsma(sb + WN_LO, 16 * ks - rBase, 2 * wn, 128, lane), bl);
            #pragma unroll
            for (int m = 0; m < 2; ++m) {
                float* c0 = C2 + m * 8;
                float* c1 = C2 + m * 8 + 4;
                mma(c0, ah[m], bh[0], bh[1]); mma(c1, ah[m], bh[2], bh[3]);
                mma(c0, ah[m], bl[0], bl[1]); mma(c1, ah[m], bl[2], bl[3]);
                mma(c0, al[m], bh[0], bh[1]); mma(c1, al[m], bh[2], bh[3]);
            }
        }
        if (chunk == 0) {
            __syncthreads();   // chunk A fully consumed
            cpblk(sb + WN_HI, g_WnHi + (size_t)i * 26624 + 14336, 12288, tid);
            cpblk(sb + WN_LO, g_WnLo + (size_t)i * 26624 + 14336, 12288, tid);
            CP_COMMIT();
            CP_WAIT0();
            __syncthreads();   // chunk B staged
        }
    }

    // ---- final epilogue: tanh + store ----
    #pragma unroll
    for (int m = 0; m < 2; ++m)
        #pragma unroll
        for (int co = 0; co < 2; ++co) {
            int d = 16 * wn + co * 8 + (lane & 3) * 2;
            int r0 = m0 + m * 16 + (lane >> 2);
            const float* c = C2 + m * 8 + co * 4;
            float2 v0 = { tanha(c[0]), tanha(c[1]) };
            float2 v1 = { tanha(c[2]), tanha(c[3]) };
            *(float2*)&out[((size_t)(b0 + r0)     * KN + i) * 64 + d] = v0;
            *(float2*)&out[((size_t)(b0 + r0 + 8) * KN + i) * 64 + d] = v1;
        }
}

extern "C" void kernel_launch(void* const* d_in, const int* in_sizes, int n_in,
                              void* d_out, int out_size)
{
    const float* states = (const float*)d_in[0];
    const float* action = (const float*)d_in[1];
    const float* W_edge = (const float*)d_in[2];
    const float* b_edge = (const float*)d_in[3];
    const float* W_node = (const float*)d_in[4];
    const float* b_node = (const float*)d_in[5];
    float* out = (float*)d_out;

    int B = in_sizes[0] / (KN * 64);   // 8192

    prep_kernel<<<2048, 256>>>(states, action, W_edge, W_node);

    cudaFuncSetAttribute(gnn_hmma_kernel,
                         cudaFuncAttributeMaxDynamicSharedMemorySize, SMEM_TOTAL);
    dim3 grid(B / TB, KN);
    gnn_hmma_kernel<<<grid, NT, SMEM_TOTAL>>>(b_edge, b_node, out);
}

// round 10
// speedup vs baseline: 1.3566x; 1.1035x over previous
#include <cuda_runtime.h>
#include <cstdint>

// TransitionGNN via legacy mma.sync.m16n8k8 TF32 (single pass).
// R10: same 2-CTA/SM skeleton as R9 (TB=64, 256 thr, 2m x 4n warps), but TF32
// replaces the 3-pass bf16 split: 33% fewer tensor instructions, same LDS bytes.
// B=8192, K=10, D=64, H=128, A=16, E=90, F=208.

#define KN 10
#define TB 64
#define NT 256

// ---- staged scratch (tf32, pre-swizzled for ldmatrix) ----
__device__ __align__(16) unsigned char g_s[KN * 8192 * 256];    // [j][b][64k] 256B rows, swz
__device__ __align__(16) unsigned char g_a[KN * 8192 * 128];    // [j][b][16a pad32] 128B rows, swz
__device__ __align__(16) unsigned char g_We[90 * 128 * 512];    // W^T [e][128h][128k] 512B rows, swz
__device__ __align__(16) unsigned char g_WnA[KN * 64 * 512];    // Wn^T [i][64d][f 0..111 pad128] swz
__device__ __align__(16) unsigned char g_WnB[KN * 64 * 512];    // Wn^T [i][64d][f 112..207 pad128] swz

// ---- smem map (bytes), total 111104 => 2 CTAs/SM ----
#define SI    0u          // 16KB (64r x 256B)
#define ACT   16384u      // 8KB  (64r x 128B)
#define BIAS  24576u      // 4608B (9 x 512)
#define SJ    29184u      // 16KB
#define WE    45568u      // 64KB W^T tile
#define SMEM_TOTAL 111104
// node-phase aliases:
#define AGG   (WE)             // 32KB (64r x 512B)
#define WN    (WE + 32768u)    // 32KB Wn chunk

__device__ __forceinline__ uint32_t tf32c(float x) {
    uint32_t r; asm("cvt.rna.tf32.f32 %0, %1;" : "=r"(r) : "f"(x)); return r;
}
__device__ __forceinline__ float tanha(float x) {
    float r; asm("tanh.approx.f32 %0, %1;" : "=f"(r) : "f"(x)); return r;
}
__device__ __forceinline__ void cp16(uint32_t s, const void* g) {
    asm volatile("cp.async.cg.shared.global [%0], [%1], 16;" :: "r"(s), "l"(g));
}
__device__ __forceinline__ void cpblk(uint32_t sdst, const void* gsrc, int bytes, int tid) {
    for (int off = tid * 16; off < bytes; off += NT * 16)
        cp16(sdst + off, (const char*)gsrc + off);
}
#define CP_COMMIT() asm volatile("cp.async.commit_group;")
#define CP_WAIT0()  asm volatile("cp.async.wait_group 0;")

__device__ __forceinline__ void ldsm4(uint32_t a, uint32_t r[4]) {
    asm volatile("ldmatrix.sync.aligned.m8n8.x4.shared.b16 {%0,%1,%2,%3}, [%4];"
        : "=r"(r[0]), "=r"(r[1]), "=r"(r[2]), "=r"(r[3]) : "r"(a));
}
__device__ __forceinline__ void ldsm2(uint32_t a, uint32_t r[2]) {
    asm volatile("ldmatrix.sync.aligned.m8n8.x2.shared.b16 {%0,%1}, [%2];"
        : "=r"(r[0]), "=r"(r[1]) : "r"(a));
}
__device__ __forceinline__ void mma8(float c[4], const uint32_t a[4], uint32_t b0, uint32_t b1) {
    asm volatile("mma.sync.aligned.m16n8k8.row.col.f32.tf32.tf32.f32 "
        "{%0,%1,%2,%3},{%4,%5,%6,%7},{%8,%9},{%0,%1,%2,%3};"
        : "+f"(c[0]), "+f"(c[1]), "+f"(c[2]), "+f"(c[3])
        : "r"(a[0]), "r"(a[1]), "r"(a[2]), "r"(a[3]), "r"(b0), "r"(b1));
}
// A-tile ldmatrix addr (x4: m16 x k8): rows r0..r0+15, chunks c0,c0+1 (16B=4 tf32)
__device__ __forceinline__ uint32_t ldsmA(uint32_t base, int r0, int c0, int S, int lane) {
    int row = r0 + (lane & 7) + ((lane >> 3) & 1) * 8;
    int chunk = c0 + (lane >> 4);
    return base + (uint32_t)(row * S) + ((uint32_t)(chunk ^ (row & 7)) << 4);
}
// B-tile ldmatrix addr (x2: n8 x k8 from W^T rows=n): rows r0..r0+7, chunks c0,c0+1
__device__ __forceinline__ uint32_t ldsmB(uint32_t base, int r0, int c0, int S, int lane) {
    int row = r0 + (lane & 7);
    int chunk = c0 + ((lane >> 3) & 1);
    return base + (uint32_t)(row * S) + ((uint32_t)(chunk ^ (row & 7)) << 4);
}

// ===================== prep kernel =====================
__global__ void prep_kernel(const float* __restrict__ states, const float* __restrict__ action,
                            const float* __restrict__ We, const float* __restrict__ Wn)
{
    int tid = blockIdx.x * blockDim.x + threadIdx.x;
    int NTH = gridDim.x * blockDim.x;
    // states -> g_s [j][b][64k], pairs over k
    for (int p = tid; p < KN * 8192 * 32; p += NTH) {
        int d2 = p & 31, b = (p >> 5) & 8191, j = p >> 18;
        float2 v = *(const float2*)&states[((size_t)b * KN + j) * 64 + 2 * d2];
        uint32_t off = ((uint32_t)(j * 8192 + b) << 8)
                     + ((uint32_t)(((d2 >> 1) ^ (b & 7))) << 4) + ((uint32_t)(d2 & 1) << 3);
        uint2 w = { tf32c(v.x), tf32c(v.y) };
        *(uint2*)(g_s + off) = w;
    }
    // action -> g_a [j][b][16a pad], pairs over a
    for (int p = tid; p < KN * 8192 * 8; p += NTH) {
        int a2 = p & 7, b = (p >> 3) & 8191, j = p >> 16;
        float2 v = *(const float2*)&action[((size_t)b * KN + j) * 16 + 2 * a2];
        uint32_t off = ((uint32_t)(j * 8192 + b) << 7)
                     + ((uint32_t)(((a2 >> 1) ^ (b & 7))) << 4) + ((uint32_t)(a2 & 1) << 3);
        uint2 w = { tf32c(v.x), tf32c(v.y) };
        *(uint2*)(g_a + off) = w;
    }
    // W_edge [e][k][h] -> g_We = W^T [e][h][k], pairs over h (coalesced reads)
    for (int p = tid; p < 90 * 128 * 64; p += NTH) {
        int h2 = p & 63, k = (p >> 6) & 127, e = p >> 13;
        float2 v = *(const float2*)&We[((size_t)e * 128 + k) * 128 + 2 * h2];
        int h0 = 2 * h2;
        uint32_t o0 = ((uint32_t)(e * 128 + h0) << 9)
                    + ((uint32_t)(((k >> 2) ^ (h0 & 7))) << 4) + ((uint32_t)(k & 3) << 2);
        uint32_t o1 = ((uint32_t)(e * 128 + h0 + 1) << 9)
                    + ((uint32_t)(((k >> 2) ^ ((h0 + 1) & 7))) << 4) + ((uint32_t)(k & 3) << 2);
        *(uint32_t*)(g_We + o0) = tf32c(v.x);
        *(uint32_t*)(g_We + o1) = tf32c(v.y);
    }
    // W_node [i][f][d] -> Wn^T chunks [i][d][f'], pairs over d (coalesced reads)
    for (int p = tid; p < KN * 208 * 32; p += NTH) {
        int d2 = p & 31, fi = p >> 5;
        int f = fi % 208, i = fi / 208;
        float2 v = *(const float2*)&Wn[((size_t)i * 208 + f) * 64 + 2 * d2];
        unsigned char* base;
        int fc;
        if (f < 112) { base = g_WnA + (size_t)i * 32768; fc = f; }
        else         { base = g_WnB + (size_t)i * 32768; fc = f - 112; }
        int d0 = 2 * d2;
        uint32_t o0 = ((uint32_t)d0 << 9)
                    + ((uint32_t)(((fc >> 2) ^ (d0 & 7))) << 4) + ((uint32_t)(fc & 3) << 2);
        uint32_t o1 = ((uint32_t)(d0 + 1) << 9)
                    + ((uint32_t)(((fc >> 2) ^ ((d0 + 1) & 7))) << 4) + ((uint32_t)(fc & 3) << 2);
        *(uint32_t*)(base + o0) = tf32c(v.x);
        *(uint32_t*)(base + o1) = tf32c(v.y);
    }
}

// ===================== main kernel =====================
extern "C" __global__ void __launch_bounds__(NT, 2)
gnn_tf32_kernel(const float* __restrict__ b_edge,   // [E,H]
                const float* __restrict__ b_node,   // [K,D]
                float* __restrict__ out)            // [B,K,D]
{
    extern __shared__ char smem[];
    const uint32_t sb = (uint32_t)__cvta_generic_to_shared(smem);

    const int i    = blockIdx.y;
    const int b0   = blockIdx.x * TB;
    const int tid  = threadIdx.x;
    const int lane = tid & 31;
    const int wid  = tid >> 5;
    const int wm   = wid & 1;    // 2 m-warps: rows 32*wm .. +31
    const int wn   = wid >> 1;   // 4 n-warps: edge cols 32*wn, node cols 16*wn
    const int m0   = 32 * wm;

    // ---- prologue: si, act, bias, sj0, W0 (one group) ----
    cpblk(sb + SI,   g_s + (size_t)(i * 8192 + b0) * 256, 16384, tid);
    cpblk(sb + ACT,  g_a + (size_t)(i * 8192 + b0) * 128, 8192, tid);
    cpblk(sb + BIAS, b_edge + (size_t)(i * 9) * 128, 4608, tid);
    {
        int j0 = (i == 0) ? 1 : 0;
        cpblk(sb + SJ, g_s + (size_t)(j0 * 8192 + b0) * 256, 16384, tid);
        cpblk(sb + WE, g_We + (size_t)(i * 9) * 65536, 65536, tid);
    }
    CP_COMMIT();

    float C[32], agg[32];
    #pragma unroll
    for (int q = 0; q < 32; ++q) agg[q] = 0.0f;

    // ---- edge loop ----
    #pragma unroll
    for (int t = 0; t < 9; ++t) {
        CP_WAIT0();
        __syncthreads();     // W_t, sj_t (t==0: +si/act/bias) visible

        // init C from bias: C[m*16 + p*4 + e], cols h = 32*wn + 8p + 2*(lane&3)
        {
            const float* bs = (const float*)(smem + BIAS) + t * 128;
            #pragma unroll
            for (int p = 0; p < 4; ++p) {
                int h = 32 * wn + 8 * p + (lane & 3) * 2;
                float2 bv = *(const float2*)&bs[h];
                #pragma unroll
                for (int m = 0; m < 2; ++m) {
                    float* c = C + m * 16 + p * 4;
                    c[0] = bv.x; c[1] = bv.y; c[2] = bv.x; c[3] = bv.y;
                }
            }
        }

        #pragma unroll
        for (int ks = 0; ks < 16; ++ks) {
            const uint32_t aB = (ks < 8) ? (sb + SI) : (sb + SJ);
            const int c0 = 2 * (ks & 7);
            uint32_t a0[4], a1[4];
            ldsm4(ldsmA(aB, m0,      c0, 256, lane), a0);
            ldsm4(ldsmA(aB, m0 + 16, c0, 256, lane), a1);
            uint32_t b[4][2];
            #pragma unroll
            for (int p = 0; p < 4; ++p)
                ldsm2(ldsmB(sb + WE, 32 * wn + 8 * p, 2 * ks, 512, lane), b[p]);
            #pragma unroll
            for (int p = 0; p < 4; ++p) {
                mma8(C + p * 4,      a0, b[p][0], b[p][1]);
                mma8(C + 16 + p * 4, a1, b[p][0], b[p][1]);
            }
        }
        __syncthreads();   // W_t / sj_t fully consumed

        // issue next loads (buffers free)
        if (t < 8) {
            int jn = (t + 1) + ((t + 1) >= i ? 1 : 0);
            cpblk(sb + SJ, g_s + (size_t)(jn * 8192 + b0) * 256, 16384, tid);
            cpblk(sb + WE, g_We + (size_t)(i * 9 + t + 1) * 65536, 65536, tid);
        } else {
            cpblk(sb + WN, g_WnA + (size_t)i * 32768, 32768, tid);
        }
        CP_COMMIT();

        // epilogue (overlaps in-flight cp.async + other CTA's MMAs)
        #pragma unroll
        for (int q = 0; q < 32; ++q) agg[q] += tanha(C[q]);
    }

    // ---- node phase: write agg as tf32 A-tile [64r][128h] (aliases WE low half) ----
    #pragma unroll
    for (int m = 0; m < 2; ++m)
        #pragma unroll
        for (int p = 0; p < 4; ++p) {
            int h = 32 * wn + 8 * p + (lane & 3) * 2;
            int idx = m * 16 + p * 4;
            #pragma unroll
            for (int hh = 0; hh < 2; ++hh) {
                int r = m0 + m * 16 + (lane >> 2) + 8 * hh;
                uint32_t off = (uint32_t)(r * 512)
                             + ((uint32_t)(((h >> 2) ^ (r & 7))) << 4)
                             + ((uint32_t)(h & 3) << 2);
                uint2 w = { tf32c(agg[idx + 2 * hh]), tf32c(agg[idx + 2 * hh + 1]) };
                *(uint2*)(smem + AGG + off) = w;
            }
        }
    CP_WAIT0();          // WnA staged
    __syncthreads();     // + AGG visible

    // init C2 from node bias: cols d = 16*wn + 8p + 2*(lane&3), p in {0,1}
    float C2[16];
    #pragma unroll
    for (int p = 0; p < 2; ++p) {
        int d = 16 * wn + 8 * p + (lane & 3) * 2;
        float2 bn = *(const float2*)&b_node[(size_t)i * 64 + d];
        #pragma unroll
        for (int m = 0; m < 2; ++m) {
            float* c = C2 + m * 8 + p * 4;
            c[0] = bn.x; c[1] = bn.y; c[2] = bn.x; c[3] = bn.y;
        }
    }

    // node GEMM: 26 k8-steps over F=208; WN chunk A = ks 0..13, chunk B = ks 14..25
    #pragma unroll
    for (int chunk = 0; chunk < 2; ++chunk) {
        const int ksBeg = chunk ? 14 : 0;
        const int ksEnd = chunk ? 26 : 14;
        #pragma unroll
        for (int ks = ksBeg; ks < ksEnd; ++ks) {
            uint32_t aB; int S, c0;
            if (ks < 8)       { aB = sb + SI;  S = 256; c0 = 2 * ks; }
            else if (ks < 10) { aB = sb + ACT; S = 128; c0 = 2 * (ks - 8); }
            else              { aB = sb + AGG; S = 512; c0 = 2 * (ks - 10); }
            uint32_t a0[4], a1[4];
            ldsm4(ldsmA(aB, m0,      c0, S, lane), a0);
            ldsm4(ldsmA(aB, m0 + 16, c0, S, lane), a1);
            const int wc = chunk ? 2 * (ks - 14) : 2 * ks;
            #pragma unroll
            for (int p = 0; p < 2; ++p) {
                uint32_t b[2];
                ldsm2(ldsmB(sb + WN, 16 * wn + 8 * p, wc, 512, lane), b);
                mma8(C2 + p * 4,     a0, b[0], b[1]);
                mma8(C2 + 8 + p * 4, a1, b[0], b[1]);
            }
        }
        if (chunk == 0) {
            __syncthreads();   // chunk A fully consumed
            cpblk(sb + WN, g_WnB + (size_t)i * 32768, 32768, tid);
            CP_COMMIT();
            CP_WAIT0();
            __syncthreads();   // chunk B staged
        }
    }

    // ---- final epilogue: tanh + store ----
    #pragma unroll
    for (int m = 0; m < 2; ++m)
        #pragma unroll
        for (int p = 0; p < 2; ++p) {
            int d = 16 * wn + 8 * p + (lane & 3) * 2;
            int r0 = m0 + m * 16 + (lane >> 2);
            const float* c = C2 + m * 8 + p * 4;
            float2 v0 = { tanha(c[0]), tanha(c[1]) };
            float2 v1 = { tanha(c[2]), tanha(c[3]) };
            *(float2*)&out[((size_t)(b0 + r0)     * KN + i) * 64 + d] = v0;
            *(float2*)&out[((size_t)(b0 + r0 + 8) * KN + i) * 64 + d] = v1;
        }
}

extern "C" void kernel_launch(void* const* d_in, const int* in_sizes, int n_in,
                              void* d_out, int out_size)
{
    const float* states = (const float*)d_in[0];
    const float* action = (const float*)d_in[1];
    const float* W_edge = (const float*)d_in[2];
    const float* b_edge = (const float*)d_in[3];
    const float* W_node = (const float*)d_in[4];
    const float* b_node = (const float*)d_in[5];
    float* out = (float*)d_out;

    int B = in_sizes[0] / (KN * 64);   // 8192

    prep_kernel<<<2048, 256>>>(states, action, W_edge, W_node);

    cudaFuncSetAttribute(gnn_tf32_kernel,
                         cudaFuncAttributeMaxDynamicSharedMemorySize, SMEM_TOTAL);
    dim3 grid(B / TB, KN);
    gnn_tf32_kernel<<<grid, NT, SMEM_TOTAL>>>(b_edge, b_node, out);
}

// round 11
// speedup vs baseline: 1.4275x; 1.0523x over previous
#include <cuda_runtime.h>
#include <cstdint>

// TransitionGNN via legacy mma.sync.m16n8k8 TF32 (single pass).
// R11: padded-stride smem layouts (no XOR swizzle -> 1 IADD per ldmatrix addr),
// all B loads via ldmatrix.x4. Same 2-CTA/SM skeleton (TB=64, 256 thr, 2m x 4n).
// B=8192, K=10, D=64, H=128, A=16, E=90, F=208.

#define KN 10
#define TB 64
#define NT 256

// padded row strides (bytes); stride/4 mod 32 == 4 or 20 -> ldmatrix conflict-free
#define S_S   272   // states rows: 256B data + 16 pad   (68 words, mod32=4)
#define S_A   80    // action rows: 64B data + 16 pad    (20 words, mod32=20)
#define S_W   528   // W^T rows:   512B data + 16 pad    (132 words, mod32=4)
#define S_WNA 464   // Wn^T chunkA rows: 448B + 16       (116 words, mod32=20)
#define S_WNB 400   // Wn^T chunkB rows: 384B + 16       (100 words, mod32=4)

// ---- staged scratch (tf32, pre-padded rows; linear within row) ----
__device__ __align__(16) unsigned char g_s[KN * 8192 * S_S];      // [j][b][64k]
__device__ __align__(16) unsigned char g_a[KN * 8192 * S_A];      // [j][b][16a]
__device__ __align__(16) unsigned char g_We[90 * 128 * S_W];      // W^T [e][128h][128k]
__device__ __align__(16) unsigned char g_WnA[KN * 64 * S_WNA];    // Wn^T [i][64d][f 0..111]
__device__ __align__(16) unsigned char g_WnB[KN * 64 * S_WNB];    // Wn^T [i][64d][f 112..207]

// ---- smem map (bytes), per CTA 112128 => 2 CTAs/SM ----
#define SI    0u                    // 64 x 272 = 17408
#define SJ    17408u                // 17408
#define ACT   34816u                // 64 x 80 = 5120
#define BIAS  39936u                // 4608 (9 x 512)
#define WE    44544u                // 128 x 528 = 67584
#define SMEM_TOTAL 112128
// node-phase aliases inside WE:
#define AGG   (WE)                  // 64 x 528 = 33792
#define WN    (WE + 33792u)         // <= 29696

__device__ __forceinline__ uint32_t tf32c(float x) {
    uint32_t r; asm("cvt.rna.tf32.f32 %0, %1;" : "=r"(r) : "f"(x)); return r;
}
__device__ __forceinline__ float tanha(float x) {
    float r; asm("tanh.approx.f32 %0, %1;" : "=f"(r) : "f"(x)); return r;
}
__device__ __forceinline__ void cp16(uint32_t s, const void* g) {
    asm volatile("cp.async.cg.shared.global [%0], [%1], 16;" :: "r"(s), "l"(g));
}
__device__ __forceinline__ void cpblk(uint32_t sdst, const void* gsrc, int bytes, int tid) {
    for (int off = tid * 16; off < bytes; off += NT * 16)
        cp16(sdst + off, (const char*)gsrc + off);
}
#define CP_COMMIT() asm volatile("cp.async.commit_group;")
#define CP_WAIT0()  asm volatile("cp.async.wait_group 0;")

__device__ __forceinline__ void ldsm4(uint32_t a, uint32_t r[4]) {
    asm volatile("ldmatrix.sync.aligned.m8n8.x4.shared.b16 {%0,%1,%2,%3}, [%4];"
        : "=r"(r[0]), "=r"(r[1]), "=r"(r[2]), "=r"(r[3]) : "r"(a));
}
__device__ __forceinline__ void mma8(float c[4], const uint32_t a[4], uint32_t b0, uint32_t b1) {
    asm volatile("mma.sync.aligned.m16n8k8.row.col.f32.tf32.tf32.f32 "
        "{%0,%1,%2,%3},{%4,%5,%6,%7},{%8,%9},{%0,%1,%2,%3};"
        : "+f"(c[0]), "+f"(c[1]), "+f"(c[2]), "+f"(c[3])
        : "r"(a[0]), "r"(a[1]), "r"(a[2]), "r"(a[3]), "r"(b0), "r"(b1));
}
// A-tile lane base: m16 x k8 x4-ldmatrix; matrices (rows r0..7,c0),(rows 8..15,c0)
// via row bit, then chunk +1 for lanes>=16. addr(ks) = base + ks*32.
__device__ __forceinline__ uint32_t baseA(uint32_t buf, int r0, int S, int lane) {
    int row = r0 + (lane & 7) + ((lane >> 3) & 1) * 8;
    return buf + (uint32_t)(row * S) + ((uint32_t)(lane >> 4) << 4);
}
// B-tile lane base: n16 x k8 x4-ldmatrix from W^T; matrices
// (n0..7,c0),(n0..7,c0+1),(n8..15,c0),(n8..15,c0+1). addr(ks) = base + ks*32.
__device__ __forceinline__ uint32_t baseB(uint32_t buf, int r0, int S, int lane) {
    int row = r0 + (lane & 7) + ((lane >> 4) << 3);
    return buf + (uint32_t)(row * S) + ((uint32_t)((lane >> 3) & 1) << 4);
}

// ===================== prep kernel =====================
__global__ void prep_kernel(const float* __restrict__ states, const float* __restrict__ action,
                            const float* __restrict__ Wed, const float* __restrict__ Wn)
{
    int tid = blockIdx.x * blockDim.x + threadIdx.x;
    int NTH = gridDim.x * blockDim.x;
    // states -> g_s rows of 272B (linear k within row)
    for (int p = tid; p < KN * 8192 * 32; p += NTH) {
        int d2 = p & 31, b = (p >> 5) & 8191, j = p >> 18;
        float2 v = *(const float2*)&states[((size_t)b * KN + j) * 64 + 2 * d2];
        uint2 w = { tf32c(v.x), tf32c(v.y) };
        *(uint2*)(g_s + (size_t)(j * 8192 + b) * S_S + d2 * 8) = w;
    }
    // action -> g_a rows of 80B
    for (int p = tid; p < KN * 8192 * 8; p += NTH) {
        int a2 = p & 7, b = (p >> 3) & 8191, j = p >> 16;
        float2 v = *(const float2*)&action[((size_t)b * KN + j) * 16 + 2 * a2];
        uint2 w = { tf32c(v.x), tf32c(v.y) };
        *(uint2*)(g_a + (size_t)(j * 8192 + b) * S_A + a2 * 8) = w;
    }
    // W_edge [e][k][h] -> g_We = W^T rows h of 528B (linear k)
    for (int p = tid; p < 90 * 128 * 64; p += NTH) {
        int h2 = p & 63, k = (p >> 6) & 127, e = p >> 13;
        float2 v = *(const float2*)&Wed[((size_t)e * 128 + k) * 128 + 2 * h2];
        int h0 = 2 * h2;
        *(uint32_t*)(g_We + (size_t)(e * 128 + h0)     * S_W + k * 4) = tf32c(v.x);
        *(uint32_t*)(g_We + (size_t)(e * 128 + h0 + 1) * S_W + k * 4) = tf32c(v.y);
    }
    // W_node [i][f][d] -> Wn^T rows d; f split at 112
    for (int p = tid; p < KN * 208 * 32; p += NTH) {
        int d2 = p & 31, fi = p >> 5;
        int f = fi % 208, i = fi / 208;
        float2 v = *(const float2*)&Wn[((size_t)i * 208 + f) * 64 + 2 * d2];
        int d0 = 2 * d2;
        if (f < 112) {
            unsigned char* base = g_WnA + (size_t)i * (64 * S_WNA);
            *(uint32_t*)(base + (size_t)d0       * S_WNA + f * 4) = tf32c(v.x);
            *(uint32_t*)(base + (size_t)(d0 + 1) * S_WNA + f * 4) = tf32c(v.y);
        } else {
            unsigned char* base = g_WnB + (size_t)i * (64 * S_WNB);
            int fc = f - 112;
            *(uint32_t*)(base + (size_t)d0       * S_WNB + fc * 4) = tf32c(v.x);
            *(uint32_t*)(base + (size_t)(d0 + 1) * S_WNB + fc * 4) = tf32c(v.y);
        }
    }
}

// ===================== main kernel =====================
extern "C" __global__ void __launch_bounds__(NT, 2)
gnn_tf32_kernel(const float* __restrict__ b_edge,   // [E,H]
                const float* __restrict__ b_node,   // [K,D]
                float* __restrict__ out)            // [B,K,D]
{
    extern __shared__ char smem[];
    const uint32_t sb = (uint32_t)__cvta_generic_to_shared(smem);

    const int i    = blockIdx.y;
    const int b0   = blockIdx.x * TB;
    const int tid  = threadIdx.x;
    const int lane = tid & 31;
    const int wid  = tid >> 5;
    const int wm   = wid & 1;    // 2 m-warps: rows 32*wm .. +31
    const int wn   = wid >> 1;   // 4 n-warps: edge cols 32*wn, node cols 16*wn
    const int m0   = 32 * wm;

    // ---- prologue: si, act, bias, sj0, W0 (one group) ----
    cpblk(sb + SI,   g_s + (size_t)(i * 8192 + b0) * S_S, TB * S_S, tid);
    cpblk(sb + ACT,  g_a + (size_t)(i * 8192 + b0) * S_A, TB * S_A, tid);
    cpblk(sb + BIAS, b_edge + (size_t)(i * 9) * 128, 4608, tid);
    {
        int j0 = (i == 0) ? 1 : 0;
        cpblk(sb + SJ, g_s + (size_t)(j0 * 8192 + b0) * S_S, TB * S_S, tid);
        cpblk(sb + WE, g_We + (size_t)(i * 9) * (128 * S_W), 128 * S_W, tid);
    }
    CP_COMMIT();

    // lane bases (loop-invariant)
    const uint32_t aSI0 = baseA(sb + SI, m0,      S_S, lane);
    const uint32_t aSI1 = baseA(sb + SI, m0 + 16, S_S, lane);
    const uint32_t aSJ0 = baseA(sb + SJ, m0,      S_S, lane);
    const uint32_t aSJ1 = baseA(sb + SJ, m0 + 16, S_S, lane);
    const uint32_t bWE0 = baseB(sb + WE, 32 * wn,      S_W, lane);
    const uint32_t bWE1 = baseB(sb + WE, 32 * wn + 16, S_W, lane);

    float C[32], agg[32];
    #pragma unroll
    for (int q = 0; q < 32; ++q) agg[q] = 0.0f;

    // ---- edge loop ----
    #pragma unroll
    for (int t = 0; t < 9; ++t) {
        CP_WAIT0();
        __syncthreads();     // W_t, sj_t (t==0: +si/act/bias) visible

        // init C from bias: C[m*16 + p*4], cols h = 32*wn + 8p + 2*(lane&3)
        {
            const float* bs = (const float*)(smem + BIAS) + t * 128;
            #pragma unroll
            for (int p = 0; p < 4; ++p) {
                int h = 32 * wn + 8 * p + (lane & 3) * 2;
                float2 bv = *(const float2*)&bs[h];
                #pragma unroll
                for (int m = 0; m < 2; ++m) {
                    float* c = C + m * 16 + p * 4;
                    c[0] = bv.x; c[1] = bv.y; c[2] = bv.x; c[3] = bv.y;
                }
            }
        }

        #pragma unroll
        for (int ks = 0; ks < 16; ++ks) {
            const uint32_t koff = (uint32_t)((ks & 7) * 32);
            uint32_t a0[4], a1[4], bA[4], bB[4];
            if (ks < 8) {
                ldsm4(aSI0 + koff, a0);
                ldsm4(aSI1 + koff, a1);
            } else {
                ldsm4(aSJ0 + koff, a0);
                ldsm4(aSJ1 + koff, a1);
            }
            ldsm4(bWE0 + (uint32_t)(ks * 32), bA);
            ldsm4(bWE1 + (uint32_t)(ks * 32), bB);
            mma8(C + 0,  a0, bA[0], bA[1]);
            mma8(C + 4,  a0, bA[2], bA[3]);
            mma8(C + 8,  a0, bB[0], bB[1]);
            mma8(C + 12, a0, bB[2], bB[3]);
            mma8(C + 16, a1, bA[0], bA[1]);
            mma8(C + 20, a1, bA[2], bA[3]);
            mma8(C + 24, a1, bB[0], bB[1]);
            mma8(C + 28, a1, bB[2], bB[3]);
        }
        __syncthreads();   // W_t / sj_t fully consumed

        // issue next loads (buffers free)
        if (t < 8) {
            int jn = (t + 1) + ((t + 1) >= i ? 1 : 0);
            cpblk(sb + SJ, g_s + (size_t)(jn * 8192 + b0) * S_S, TB * S_S, tid);
            cpblk(sb + WE, g_We + (size_t)(i * 9 + t + 1) * (128 * S_W), 128 * S_W, tid);
        } else {
            cpblk(sb + WN, g_WnA + (size_t)i * (64 * S_WNA), 64 * S_WNA, tid);
        }
        CP_COMMIT();

        // epilogue (overlaps in-flight cp.async + other CTA's MMAs)
        #pragma unroll
        for (int q = 0; q < 32; ++q) agg[q] += tanha(C[q]);
    }

    // ---- node phase: write agg as tf32 A-tile [64r][128h], rows of 528B ----
    #pragma unroll
    for (int m = 0; m < 2; ++m)
        #pragma unroll
        for (int p = 0; p < 4; ++p) {
            int h = 32 * wn + 8 * p + (lane & 3) * 2;
            int idx = m * 16 + p * 4;
            #pragma unroll
            for (int hh = 0; hh < 2; ++hh) {
                int r = m0 + m * 16 + (lane >> 2) + 8 * hh;
                uint2 w = { tf32c(agg[idx + 2 * hh]), tf32c(agg[idx + 2 * hh + 1]) };
                *(uint2*)(smem + AGG + (uint32_t)(r * S_W) + (uint32_t)(h * 4)) = w;
            }
        }
    CP_WAIT0();          // WnA staged
    __syncthreads();     // + AGG visible

    // node lane bases
    const uint32_t aACT0 = baseA(sb + ACT, m0,      S_A, lane);
    const uint32_t aACT1 = baseA(sb + ACT, m0 + 16, S_A, lane);
    const uint32_t aAG0  = baseA(sb + AGG, m0,      S_W, lane);
    const uint32_t aAG1  = baseA(sb + AGG, m0 + 16, S_W, lane);

    // init C2 from node bias: cols d = 16*wn + 8p + 2*(lane&3), p in {0,1}
    float C2[16];
    #pragma unroll
    for (int p = 0; p < 2; ++p) {
        int d = 16 * wn + 8 * p + (lane & 3) * 2;
        float2 bn = *(const float2*)&b_node[(size_t)i * 64 + d];
        #pragma unroll
        for (int m = 0; m < 2; ++m) {
            float* c = C2 + m * 8 + p * 4;
            c[0] = bn.x; c[1] = bn.y; c[2] = bn.x; c[3] = bn.y;
        }
    }

    // node GEMM: 26 k8-steps over F=208; WN chunkA = ks 0..13 (f0..111),
    // chunkB = ks 14..25 (f112..207)
    #pragma unroll
    for (int chunk = 0; chunk < 2; ++chunk) {
        const int S_WN = chunk ? S_WNB : S_WNA;
        const uint32_t bWN = baseB(sb + WN, 16 * wn, S_WN, lane);
        const int ksBeg = chunk ? 14 : 0;
        const int ksEnd = chunk ? 26 : 14;
        #pragma unroll
        for (int ks = ksBeg; ks < ksEnd; ++ks) {
            uint32_t a0[4], a1[4], bN[4];
            if (ks < 8) {
                ldsm4(aSI0 + (uint32_t)(ks * 32), a0);
                ldsm4(aSI1 + (uint32_t)(ks * 32), a1);
            } else if (ks < 10) {
                ldsm4(aACT0 + (uint32_t)((ks - 8) * 32), a0);
                ldsm4(aACT1 + (uint32_t)((ks - 8) * 32), a1);
            } else {
                ldsm4(aAG0 + (uint32_t)((ks - 10) * 32), a0);
                ldsm4(aAG1 + (uint32_t)((ks - 10) * 32), a1);
            }
            ldsm4(bWN + (uint32_t)((ks - ksBeg) * 32), bN);
            mma8(C2 + 0,  a0, bN[0], bN[1]);
            mma8(C2 + 4,  a0, bN[2], bN[3]);
            mma8(C2 + 8,  a1, bN[0], bN[1]);
            mma8(C2 + 12, a1, bN[2], bN[3]);
        }
        if (chunk == 0) {
            __syncthreads();   // chunk A fully consumed
            cpblk(sb + WN, g_WnB + (size_t)i * (64 * S_WNB), 64 * S_WNB, tid);
            CP_COMMIT();
            CP_WAIT0();
            __syncthreads();   // chunk B staged
        }
    }

    // ---- final epilogue: tanh + store ----
    #pragma unroll
    for (int m = 0; m < 2; ++m)
        #pragma unroll
        for (int p = 0; p < 2; ++p) {
            int d = 16 * wn + 8 * p + (lane & 3) * 2;
            int r0 = m0 + m * 16 + (lane >> 2);
            const float* c = C2 + m * 8 + p * 4;
            float2 v0 = { tanha(c[0]), tanha(c[1]) };
            float2 v1 = { tanha(c[2]), tanha(c[3]) };
            *(float2*)&out[((size_t)(b0 + r0)     * KN + i) * 64 + d] = v0;
            *(float2*)&out[((size_t)(b0 + r0 + 8) * KN + i) * 64 + d] = v1;
        }
}

extern "C" void kernel_launch(void* const* d_in, const int* in_sizes, int n_in,
                              void* d_out, int out_size)
{
    const float* states = (const float*)d_in[0];
    const float* action = (const float*)d_in[1];
    const float* W_edge = (const float*)d_in[2];
    const float* b_edge = (const float*)d_in[3];
    const float* W_node = (const float*)d_in[4];
    const float* b_node = (const float*)d_in[5];
    float* out = (float*)d_out;

    int B = in_sizes[0] / (KN * 64);   // 8192

    prep_kernel<<<2048, 256>>>(states, action, W_edge, W_node);

    cudaFuncSetAttribute(gnn_tf32_kernel,
                         cudaFuncAttributeMaxDynamicSharedMemorySize, SMEM_TOTAL);
    dim3 grid(B / TB, KN);
    gnn_tf32_kernel<<<grid, NT, SMEM_TOTAL>>>(b_edge, b_node, out);
}